// round 12
// baseline (speedup 1.0000x reference)
#include <cuda_runtime.h>
#include <cuda_fp16.h>
#include <math.h>
#include <stdint.h>

#define B_ 4
#define L_ 384
#define H_ 128
#define F_ 384

typedef unsigned short ushort_t;

// ---------------- device scratch: transposed fp16 weight images --------------
__device__ __align__(16) ushort_t g_fw1T[F_ * H_];   // 384 x 128, [n][k]
__device__ __align__(16) ushort_t g_fw2T[F_ * F_];   // 384 x 384, [n][k]
__device__ float g_acc[B_];

// ---------------- smem layout (bytes) ----------------------------------------
#define LDE   136   // halves per row (E tile: 64 x 128)
#define LDWH  72    // halves per row (W half-tile: 128 n x 64 k)
#define LDA1  392   // halves per row (A1: 64 x 384)

#define SM_E     0        // 17408
#define SM_A1    17408    // 50176
#define SM_W0    67584    // 18432
#define SM_W1    86016    // 18432
#define SM_XCV   104448   // 384 f
#define SM_H1    105984   // 128 f
#define SM_H2    106496   // 64 f
#define SM_TOTAL 106752

// exact gelu (head MLP only)
__device__ __forceinline__ float gelu_f(float x) {
    return 0.5f * x * (1.0f + erff(x * 0.7071067811865475f));
}

// fast fp32 gelu (contraction epilogue)
__device__ __forceinline__ float gelu_fast(float x) {
    float u = 0.7978845608028654f * x * (1.0f + 0.044715f * x * x);
    float t;
    asm("tanh.approx.f32 %0, %1;" : "=f"(t) : "f"(u));
    return 0.5f * x * (1.0f + t);
}

// packed half2 gelu with HW tanh.approx.f16x2 (GEMM1 epilogue; A1 is fp16 anyway)
__device__ __forceinline__ uint32_t gelu_h2(__half2 x) {
    const __half2 c1  = __float2half2_rn(0.7978845608f);
    const __half2 c2  = __float2half2_rn(0.044715f);
    const __half2 one = __float2half2_rn(1.0f);
    const __half2 hlf = __float2half2_rn(0.5f);
    __half2 x2 = __hmul2(x, x);
    __half2 p  = __hfma2(c2, x2, one);
    __half2 u  = __hmul2(__hmul2(c1, x), p);
    uint32_t uu = *(uint32_t*)&u, tt;
    asm("tanh.approx.f16x2 %0, %1;" : "=r"(tt) : "r"(uu));
    __half2 t  = *(__half2*)&tt;
    __half2 hx = __hmul2(hlf, x);
    __half2 r  = __hfma2(hx, t, hx);
    return *(uint32_t*)&r;
}

__device__ __forceinline__ uint32_t smem_u32(const void* p) {
    uint32_t a;
    asm("{ .reg .u64 t; cvta.to.shared.u64 t, %1; cvt.u32.u64 %0, t; }" : "=r"(a) : "l"(p));
    return a;
}

#define LDSM4(r, addr) \
    asm volatile("ldmatrix.sync.aligned.m8n8.x4.shared.b16 {%0,%1,%2,%3}, [%4];" \
        : "=r"((r)[0]), "=r"((r)[1]), "=r"((r)[2]), "=r"((r)[3]) : "r"(addr))

#define CP16(dst, src) \
    asm volatile("cp.async.cg.shared.global [%0], [%1], 16;" :: "r"(dst), "l"(src) : "memory")
#define CP_COMMIT() asm volatile("cp.async.commit_group;" ::: "memory")
#define CP_WAIT0()  asm volatile("cp.async.wait_group 0;"  ::: "memory")

__device__ __forceinline__ void mma16816(float d[4], uint32_t a0, uint32_t a1,
                                         uint32_t a2, uint32_t a3,
                                         uint32_t b0, uint32_t b1) {
    asm volatile(
        "mma.sync.aligned.m16n8k16.row.col.f32.f16.f16.f32 "
        "{%0,%1,%2,%3}, {%4,%5,%6,%7}, {%8,%9}, {%0,%1,%2,%3};"
        : "+f"(d[0]), "+f"(d[1]), "+f"(d[2]), "+f"(d[3])
        : "r"(a0), "r"(a1), "r"(a2), "r"(a3), "r"(b0), "r"(b1));
}

__device__ __forceinline__ uint32_t pack_h2(float a, float b) {
    __half2 h = __floats2half2_rn(a, b);
    return *(uint32_t*)&h;
}

// issue cp.async for weight half-stage h (0..23, mt-periodic)
__device__ __forceinline__ void cp_half(int h, int tid, uint32_t sb) {
    uint32_t dstbase = sb + (uint32_t)((h & 1) ? SM_W1 : SM_W0);
    const uint4* src;
    int stride_u4;
    if (h < 6) {
        int nc = h >> 1, kh = h & 1;
        src = (const uint4*)g_fw1T + ((size_t)nc * 128) * 16 + kh * 8;
        stride_u4 = 16;
    } else {
        int j = h - 6;
        int nc2 = j / 6;
        int rem = j - nc2 * 6;
        int kc = rem >> 1, kh = rem & 1;
        src = (const uint4*)g_fw2T + ((size_t)nc2 * 128) * 48 + kc * 16 + kh * 8;
        stride_u4 = 48;
    }
#pragma unroll
    for (int it = 0; it < 4; ++it) {
        int i = tid + it * 256;
        int row = i >> 3, c = i & 7;
        uint32_t d = dstbase + row * (LDWH * 2) + c * 16;
        CP16(d, (const char*)(src + (size_t)row * stride_u4 + c));
    }
}

// 4 k-steps (one 64-k half) of single-pass fp16 MMA over a 32x32 warp tile
template <int LDA>
__device__ __forceinline__ void do_ksteps4(uint32_t aA, uint32_t bW, float acc[2][4][4])
{
#pragma unroll
    for (int ks = 0; ks < 4; ++ks) {
        uint32_t A[2][4], Bf[2][4];
        LDSM4(A[0], aA);
        LDSM4(A[1], aA + 16 * LDA * 2);
        LDSM4(Bf[0], bW);
        LDSM4(Bf[1], bW + 16 * LDWH * 2);
        aA += 32; bW += 32;
#pragma unroll
        for (int mi = 0; mi < 2; ++mi)
#pragma unroll
            for (int p = 0; p < 2; ++p) {
                mma16816(acc[mi][2*p],   A[mi][0], A[mi][1], A[mi][2], A[mi][3],
                         Bf[p][0], Bf[p][1]);
                mma16816(acc[mi][2*p+1], A[mi][0], A[mi][1], A[mi][2], A[mi][3],
                         Bf[p][2], Bf[p][3]);
            }
    }
}

// ---------------- weight prep ------------------------------------------------
__global__ void prep_weights(const float* __restrict__ fw1,
                             const float* __restrict__ fw2) {
    int idx = blockIdx.x * blockDim.x + threadIdx.x;
    int stride = gridDim.x * blockDim.x;
    for (int e = idx; e < F_ * H_; e += stride) {
        int n = e / H_, k = e % H_;
        __half h = __float2half_rn(fw1[(size_t)k * F_ + n]);
        g_fw1T[e] = *(ushort_t*)&h;
    }
    for (int e = idx; e < F_ * F_; e += stride) {
        int n = e / F_, k = e % F_;
        __half h = __float2half_rn(fw2[(size_t)k * F_ + n]);
        g_fw2T[e] = *(ushort_t*)&h;
    }
}

__global__ void zero_acc_k() {
    if (threadIdx.x < B_) g_acc[threadIdx.x] = 0.f;
}

__global__ void dummy_k() {}

__global__ __launch_bounds__(256, 2) void fused_mma(
    const float* __restrict__ hV,  const float* __restrict__ hE,
    const float* __restrict__ mask,
    const float* __restrict__ fb1, const float* __restrict__ fb2,
    const float* __restrict__ hw1, const float* __restrict__ hb1,
    const float* __restrict__ hw2, const float* __restrict__ hb2,
    const float* __restrict__ hw3, const float* __restrict__ hb3)
{
    extern __shared__ char smem[];
    ushort_t* sE  = (ushort_t*)(smem + SM_E);
    ushort_t* sA1 = (ushort_t*)(smem + SM_A1);
    float* xcv   = (float*)(smem + SM_XCV);
    float* sH1   = (float*)(smem + SM_H1);
    float* sH2   = (float*)(smem + SM_H2);

    const uint32_t sb = smem_u32(smem);

    const int tid  = threadIdx.x;
    const int wid  = tid >> 5;
    const int lane = tid & 31;
    const int g    = lane >> 2;
    const int t    = lane & 3;
    const int m0w  = (wid >> 2) * 32;
    const int n0w  = (wid & 3) * 32;
    const int l = blockIdx.x, b = blockIdx.y;

    // zero the shared x_conv accumulator (ordered by later pipeline syncs)
    if (tid < 192) {
        xcv[tid] = 0.f;
        xcv[tid + 192] = 0.f;
    }

    // ldmatrix per-lane addressing
    const int rA = lane & 15;
    const int kA = (lane >> 4) * 8;
    const int rB = (lane & 7) + (lane >> 4) * 8;
    const int kB = ((lane >> 3) & 1) * 8;

    const uint32_t aE  = sb + SM_E  + ((m0w + rA) * LDE  + kA) * 2;
    const uint32_t aA1 = sb + SM_A1 + ((m0w + rA) * LDA1 + kA) * 2;
    const uint32_t bW0 = sb + SM_W0 + ((n0w + rB) * LDWH + kB) * 2;

    const float* hE_base = hE + (size_t)(b * L_ + l) * L_ * H_;

    int hseq = 0;
    cp_half(0, tid, sb);
    CP_COMMIT();

    for (int mt = 0; mt < 6; ++mt) {
        // ---- stage E tile [64 x 128] fp32 -> fp16 (visible at next sync) ----
        {
            const float* src = hE_base + (size_t)(mt * 64) * H_;
#pragma unroll
            for (int it = 0; it < 8; ++it) {
                int gx = tid + it * 256;
                int m = gx >> 5, k4 = (gx & 31) * 4;
                float4 v = *(const float4*)(src + (size_t)m * H_ + k4);
                *(uint2*)&sE[m * LDE + k4] =
                    make_uint2(pack_h2(v.x, v.y), pack_h2(v.z, v.w));
            }
        }

        // ---- GEMM1: A1 = gelu(E @ fw1 + fb1) -> sA1 fp16 ----
        for (int nc = 0; nc < 3; ++nc) {
            float acc[2][4][4];
#pragma unroll
            for (int mi = 0; mi < 2; ++mi)
#pragma unroll
                for (int ni = 0; ni < 4; ++ni)
#pragma unroll
                    for (int r = 0; r < 4; ++r) acc[mi][ni][r] = 0.f;

            for (int kh = 0; kh < 2; ++kh) {
                CP_WAIT0();
                __syncthreads();
                int nxt = hseq + 1; if (nxt == 24) nxt = 0;
                cp_half(nxt, tid, sb);
                CP_COMMIT();
                do_ksteps4<LDE>(aE + kh * 128,
                                bW0 + (uint32_t)(hseq & 1) * (SM_W1 - SM_W0), acc);
                hseq = nxt;
            }

            // epilogue: +bias, h2 gelu, fp16 store
#pragma unroll
            for (int mi = 0; mi < 2; ++mi)
#pragma unroll
                for (int ni = 0; ni < 4; ++ni) {
                    int r = m0w + mi * 16 + g;
                    int c = nc * 128 + n0w + ni * 8 + t * 2;
                    float b0 = __ldg(&fb1[c]), b1 = __ldg(&fb1[c + 1]);
                    __half2 x01 = __floats2half2_rn(acc[mi][ni][0] + b0,
                                                    acc[mi][ni][1] + b1);
                    __half2 x23 = __floats2half2_rn(acc[mi][ni][2] + b0,
                                                    acc[mi][ni][3] + b1);
                    *(uint32_t*)&sA1[r * LDA1 + c]       = gelu_h2(x01);
                    *(uint32_t*)&sA1[(r + 8) * LDA1 + c] = gelu_h2(x23);
                }
        }

        // ---- GEMM2: Wf = gelu(A1 @ fw2 + fb2); fused register contraction ----
        for (int nc2 = 0; nc2 < 3; ++nc2) {
            float acc[2][4][4];
#pragma unroll
            for (int mi = 0; mi < 2; ++mi)
#pragma unroll
                for (int ni = 0; ni < 4; ++ni)
#pragma unroll
                    for (int r = 0; r < 4; ++r) acc[mi][ni][r] = 0.f;

            for (int kc = 0; kc < 3; ++kc)
                for (int kh = 0; kh < 2; ++kh) {
                    CP_WAIT0();
                    __syncthreads();
                    int nxt = hseq + 1; if (nxt == 24) nxt = 0;
                    cp_half(nxt, tid, sb);
                    CP_COMMIT();
                    do_ksteps4<LDA1>(aA1 + kc * 256 + kh * 128,
                                     bW0 + (uint32_t)(hseq & 1) * (SM_W1 - SM_W0), acc);
                    hseq = nxt;
                }

            // fused epilogue: gelu from acc, multiply hV, reduce, atomic into xcv
            {
                float colacc[8];
#pragma unroll
                for (int i = 0; i < 8; ++i) colacc[i] = 0.f;
                const float* hvb = hV + ((size_t)(b * L_) + mt * 64) * F_ + nc2 * 128;
#pragma unroll
                for (int mi = 0; mi < 2; ++mi) {
                    int r = m0w + mi * 16 + g;
                    // batch the 8 hV loads for this mi before the gelu chain
                    float2 hv0[4], hv1[4];
#pragma unroll
                    for (int ni = 0; ni < 4; ++ni) {
                        int cc = n0w + ni * 8 + t * 2;
                        hv0[ni] = *(const float2*)(hvb + (size_t)r * F_ + cc);
                        hv1[ni] = *(const float2*)(hvb + (size_t)(r + 8) * F_ + cc);
                    }
#pragma unroll
                    for (int ni = 0; ni < 4; ++ni) {
                        int c = nc2 * 128 + n0w + ni * 8 + t * 2;
                        float b0 = __ldg(&fb2[c]), b1 = __ldg(&fb2[c + 1]);
                        colacc[ni * 2 + 0] += gelu_fast(acc[mi][ni][0] + b0) * hv0[ni].x
                                            + gelu_fast(acc[mi][ni][2] + b0) * hv1[ni].x;
                        colacc[ni * 2 + 1] += gelu_fast(acc[mi][ni][1] + b1) * hv0[ni].y
                                            + gelu_fast(acc[mi][ni][3] + b1) * hv1[ni].y;
                    }
                }
#pragma unroll
                for (int i = 0; i < 8; ++i) {
                    colacc[i] += __shfl_down_sync(0xffffffffu, colacc[i], 16);
                    colacc[i] += __shfl_down_sync(0xffffffffu, colacc[i], 8);
                    colacc[i] += __shfl_down_sync(0xffffffffu, colacc[i], 4);
                }
                if (lane < 4) {
#pragma unroll
                    for (int ni = 0; ni < 4; ++ni) {
                        int f = nc2 * 128 + n0w + ni * 8 + lane * 2;
                        atomicAdd(&xcv[f],     colacc[ni * 2 + 0]);
                        atomicAdd(&xcv[f + 1], colacc[ni * 2 + 1]);
                    }
                }
            }
            // no extra sync: next pipeline sync (or final sync) orders xcv
        }
    }

    CP_WAIT0();   // retire final wrapped prefetch

    // ---- head MLP (exact gelu) ----
    __syncthreads();   // all atomics into xcv complete
    if (tid < 128) {
        float s = hb1[tid];
#pragma unroll 4
        for (int i = 0; i < F_; ++i) s += xcv[i] * hw1[i * H_ + tid];
        sH1[tid] = gelu_f(s);
    }
    __syncthreads();
    if (tid < 64) {
        float s = hb2[tid];
#pragma unroll 4
        for (int i = 0; i < H_; ++i) s += sH1[i] * hw2[i * 64 + tid];
        sH2[tid] = gelu_f(s);
    }
    __syncthreads();
    if (tid < 32) {
        float p = sH2[tid] * hw3[tid] + sH2[tid + 32] * hw3[tid + 32];
#pragma unroll
        for (int o = 16; o > 0; o >>= 1) p += __shfl_down_sync(0xffffffffu, p, o);
        if (tid == 0) {
            float pred = p + hb3[0];
            atomicAdd(&g_acc[b], pred * mask[b * L_ + l]);
        }
    }
}

__global__ void finalize_k(const float* __restrict__ mask, float* __restrict__ out) {
    int b = threadIdx.y, lane = threadIdx.x;
    float s = 0.f;
    for (int l = lane; l < L_; l += 32) s += mask[b * L_ + l];
#pragma unroll
    for (int o = 16; o > 0; o >>= 1) s += __shfl_down_sync(0xffffffffu, s, o);
    if (lane == 0) out[b] = g_acc[b] / sqrtf(fmaxf(s, 1.0f));
}

extern "C" void kernel_launch(void* const* d_in, const int* in_sizes, int n_in,
                              void* d_out, int out_size)
{
    const float* hV   = (const float*)d_in[0];
    const float* hE   = (const float*)d_in[1];
    const float* mask = (const float*)d_in[2];
    const float* fw1  = (const float*)d_in[3];
    const float* fb1  = (const float*)d_in[4];
    const float* fw2  = (const float*)d_in[5];
    const float* fb2  = (const float*)d_in[6];
    const float* hw1  = (const float*)d_in[7];
    const float* hb1  = (const float*)d_in[8];
    const float* hw2  = (const float*)d_in[9];
    const float* hb2  = (const float*)d_in[10];
    const float* hw3  = (const float*)d_in[11];
    const float* hb3  = (const float*)d_in[12];
    float* out = (float*)d_out;

    cudaFuncSetAttribute(fused_mma, cudaFuncAttributeMaxDynamicSharedMemorySize, SM_TOTAL);

    // 2 harness launches precede ours; with exactly 1 dummy, fused_mma is
    // launch index 5 -> ncu "-s 5 -c 1" profiles it.
    prep_weights<<<96, 256>>>(fw1, fw2);
    zero_acc_k<<<1, 32>>>();
    dummy_k<<<1, 32>>>();
    dim3 grid(L_, B_);
    fused_mma<<<grid, 256, SM_TOTAL>>>(hV, hE, mask, fb1, fb2,
                                       hw1, hb1, hw2, hb2, hw3, hb3);
    finalize_k<<<1, dim3(32, B_)>>>(mask, out);
}

// round 13
// speedup vs baseline: 1.0180x; 1.0180x over previous
#include <cuda_runtime.h>
#include <cuda_fp16.h>
#include <math.h>
#include <stdint.h>

#define B_ 4
#define L_ 384
#define H_ 128
#define F_ 384

typedef unsigned short ushort_t;

// ---------------- device scratch: transposed fp16 weight images --------------
__device__ __align__(16) ushort_t g_fw1T[F_ * H_];   // 384 x 128, [n][k]
__device__ __align__(16) ushort_t g_fw2T[F_ * F_];   // 384 x 384, [n][k]
__device__ float g_acc[B_];

// ---------------- smem layout (bytes) ----------------------------------------
#define LDE   136   // halves per row (E tile: 64 x 128)
#define LDWH  72    // halves per row (W half-tile: 128 n x 64 k)
#define LDA1  392   // halves per row (A1: 64 x 384)

#define SM_E     0        // 17408
#define SM_A1    17408    // 50176
#define SM_W0    67584    // 18432
#define SM_W1    86016    // 18432
#define SM_XCV   104448   // 384 f
#define SM_PART  105984   // 256 f
#define SM_H1    107008   // 128 f
#define SM_H2    107520   // 64 f
#define SM_TOTAL 107776

// exact gelu (head MLP only)
__device__ __forceinline__ float gelu_f(float x) {
    return 0.5f * x * (1.0f + erff(x * 0.7071067811865475f));
}

// fast gelu: tanh formulation with HW MUFU.TANH
__device__ __forceinline__ float gelu_fast(float x) {
    float u = 0.7978845608028654f * x * (1.0f + 0.044715f * x * x);
    float t;
    asm("tanh.approx.f32 %0, %1;" : "=f"(t) : "f"(u));
    return 0.5f * x * (1.0f + t);
}

__device__ __forceinline__ uint32_t smem_u32(const void* p) {
    uint32_t a;
    asm("{ .reg .u64 t; cvta.to.shared.u64 t, %1; cvt.u32.u64 %0, t; }" : "=r"(a) : "l"(p));
    return a;
}

#define LDSM4(r, addr) \
    asm volatile("ldmatrix.sync.aligned.m8n8.x4.shared.b16 {%0,%1,%2,%3}, [%4];" \
        : "=r"((r)[0]), "=r"((r)[1]), "=r"((r)[2]), "=r"((r)[3]) : "r"(addr))

#define CP16(dst, src) \
    asm volatile("cp.async.cg.shared.global [%0], [%1], 16;" :: "r"(dst), "l"(src) : "memory")
#define CP_COMMIT() asm volatile("cp.async.commit_group;" ::: "memory")
#define CP_WAIT0()  asm volatile("cp.async.wait_group 0;"  ::: "memory")

__device__ __forceinline__ void mma16816(float d[4], uint32_t a0, uint32_t a1,
                                         uint32_t a2, uint32_t a3,
                                         uint32_t b0, uint32_t b1) {
    asm volatile(
        "mma.sync.aligned.m16n8k16.row.col.f32.f16.f16.f32 "
        "{%0,%1,%2,%3}, {%4,%5,%6,%7}, {%8,%9}, {%0,%1,%2,%3};"
        : "+f"(d[0]), "+f"(d[1]), "+f"(d[2]), "+f"(d[3])
        : "r"(a0), "r"(a1), "r"(a2), "r"(a3), "r"(b0), "r"(b1));
}

__device__ __forceinline__ uint32_t pack_h2(float a, float b) {
    __half2 h = __floats2half2_rn(a, b);
    return *(uint32_t*)&h;
}

// issue cp.async for weight half-stage h (0..23, mt-periodic)
__device__ __forceinline__ void cp_half(int h, int tid, uint32_t sb) {
    uint32_t dstbase = sb + (uint32_t)((h & 1) ? SM_W1 : SM_W0);
    const uint4* src;
    int stride_u4;
    if (h < 6) {
        int nc = h >> 1, kh = h & 1;
        src = (const uint4*)g_fw1T + ((size_t)nc * 128) * 16 + kh * 8;
        stride_u4 = 16;
    } else {
        int j = h - 6;
        int nc2 = j / 6;
        int rem = j - nc2 * 6;
        int kc = rem >> 1, kh = rem & 1;
        src = (const uint4*)g_fw2T + ((size_t)nc2 * 128) * 48 + kc * 16 + kh * 8;
        stride_u4 = 48;
    }
#pragma unroll
    for (int it = 0; it < 4; ++it) {
        int i = tid + it * 256;
        int row = i >> 3, c = i & 7;
        uint32_t d = dstbase + row * (LDWH * 2) + c * 16;
        CP16(d, (const char*)(src + (size_t)row * stride_u4 + c));
    }
}

// 4 k-steps (one 64-k half), fragments software-pipelined:
// LDSM for k-step ks+1 issues before the HMMAs of ks consume their frags.
template <int LDA>
__device__ __forceinline__ void do_ksteps4(uint32_t aA, uint32_t bW, float acc[2][4][4])
{
    uint32_t A[2][4], Bf[2][4];
    LDSM4(A[0], aA);
    LDSM4(A[1], aA + 16 * LDA * 2);
    LDSM4(Bf[0], bW);
    LDSM4(Bf[1], bW + 16 * LDWH * 2);
#pragma unroll
    for (int ks = 0; ks < 4; ++ks) {
        uint32_t An[2][4], Bn[2][4];
        if (ks < 3) {
            uint32_t a2 = aA + (ks + 1) * 32;
            uint32_t b2 = bW + (ks + 1) * 32;
            LDSM4(An[0], a2);
            LDSM4(An[1], a2 + 16 * LDA * 2);
            LDSM4(Bn[0], b2);
            LDSM4(Bn[1], b2 + 16 * LDWH * 2);
        }
#pragma unroll
        for (int mi = 0; mi < 2; ++mi)
#pragma unroll
            for (int p = 0; p < 2; ++p) {
                mma16816(acc[mi][2*p],   A[mi][0], A[mi][1], A[mi][2], A[mi][3],
                         Bf[p][0], Bf[p][1]);
                mma16816(acc[mi][2*p+1], A[mi][0], A[mi][1], A[mi][2], A[mi][3],
                         Bf[p][2], Bf[p][3]);
            }
        if (ks < 3) {
#pragma unroll
            for (int i = 0; i < 4; ++i) {
                A[0][i] = An[0][i]; A[1][i] = An[1][i];
                Bf[0][i] = Bn[0][i]; Bf[1][i] = Bn[1][i];
            }
        }
    }
}

// ---------------- weight prep ------------------------------------------------
__global__ void prep_weights(const float* __restrict__ fw1,
                             const float* __restrict__ fw2) {
    int idx = blockIdx.x * blockDim.x + threadIdx.x;
    int stride = gridDim.x * blockDim.x;
    for (int e = idx; e < F_ * H_; e += stride) {
        int n = e / H_, k = e % H_;
        __half h = __float2half_rn(fw1[(size_t)k * F_ + n]);
        g_fw1T[e] = *(ushort_t*)&h;
    }
    for (int e = idx; e < F_ * F_; e += stride) {
        int n = e / F_, k = e % F_;
        __half h = __float2half_rn(fw2[(size_t)k * F_ + n]);
        g_fw2T[e] = *(ushort_t*)&h;
    }
}

__global__ void zero_acc_k() {
    if (threadIdx.x < B_) g_acc[threadIdx.x] = 0.f;
}

__global__ void dummy_k() {}

__global__ __launch_bounds__(256, 2) void fused_mma(
    const float* __restrict__ hV,  const float* __restrict__ hE,
    const float* __restrict__ mask,
    const float* __restrict__ fb1, const float* __restrict__ fb2,
    const float* __restrict__ hw1, const float* __restrict__ hb1,
    const float* __restrict__ hw2, const float* __restrict__ hb2,
    const float* __restrict__ hw3, const float* __restrict__ hb3)
{
    extern __shared__ char smem[];
    ushort_t* sE  = (ushort_t*)(smem + SM_E);
    ushort_t* sA1 = (ushort_t*)(smem + SM_A1);
    float* xcv   = (float*)(smem + SM_XCV);
    float* sPart = (float*)(smem + SM_PART);
    float* sH1   = (float*)(smem + SM_H1);
    float* sH2   = (float*)(smem + SM_H2);

    const uint32_t sb = smem_u32(smem);

    const int tid  = threadIdx.x;
    const int wid  = tid >> 5;
    const int lane = tid & 31;
    const int g    = lane >> 2;
    const int t    = lane & 3;
    const int m0w  = (wid >> 2) * 32;
    const int n0w  = (wid & 3) * 32;
    const int l = blockIdx.x, b = blockIdx.y;

    // ldmatrix per-lane addressing
    const int rA = lane & 15;
    const int kA = (lane >> 4) * 8;
    const int rB = (lane & 7) + (lane >> 4) * 8;
    const int kB = ((lane >> 3) & 1) * 8;

    const uint32_t aE  = sb + SM_E  + ((m0w + rA) * LDE  + kA) * 2;
    const uint32_t aA1 = sb + SM_A1 + ((m0w + rA) * LDA1 + kA) * 2;
    const uint32_t bW0 = sb + SM_W0 + ((n0w + rB) * LDWH + kB) * 2;

    float xacc0 = 0.f, xacc1 = 0.f, xacc2 = 0.f;
    const float* hE_base = hE + (size_t)(b * L_ + l) * L_ * H_;

    int hseq = 0;
    cp_half(0, tid, sb);
    CP_COMMIT();

    for (int mt = 0; mt < 6; ++mt) {
        // ---- stage E tile [64 x 128] fp32 -> fp16 (visible at next sync) ----
        {
            const float* src = hE_base + (size_t)(mt * 64) * H_;
#pragma unroll
            for (int it = 0; it < 8; ++it) {
                int gx = tid + it * 256;
                int m = gx >> 5, k4 = (gx & 31) * 4;
                float4 v = *(const float4*)(src + (size_t)m * H_ + k4);
                *(uint2*)&sE[m * LDE + k4] =
                    make_uint2(pack_h2(v.x, v.y), pack_h2(v.z, v.w));
            }
        }

        // ---- GEMM1: A1 = gelu(E @ fw1 + fb1) -> sA1 fp16 ----
        for (int nc = 0; nc < 3; ++nc) {
            float acc[2][4][4];
#pragma unroll
            for (int mi = 0; mi < 2; ++mi)
#pragma unroll
                for (int ni = 0; ni < 4; ++ni)
#pragma unroll
                    for (int r = 0; r < 4; ++r) acc[mi][ni][r] = 0.f;

            for (int kh = 0; kh < 2; ++kh) {
                CP_WAIT0();          // cp for half hseq complete
                __syncthreads();     // visible; prior readers of other buf done
                int nxt = hseq + 1; if (nxt == 24) nxt = 0;
                cp_half(nxt, tid, sb);
                CP_COMMIT();
                do_ksteps4<LDE>(aE + kh * 128,
                                bW0 + (uint32_t)(hseq & 1) * (SM_W1 - SM_W0), acc);
                hseq = nxt;
            }

            // epilogue: +bias, fast gelu, fp16 store
#pragma unroll
            for (int mi = 0; mi < 2; ++mi)
#pragma unroll
                for (int ni = 0; ni < 4; ++ni) {
                    int r = m0w + mi * 16 + g;
                    int c = nc * 128 + n0w + ni * 8 + t * 2;
                    float b0 = __ldg(&fb1[c]), b1 = __ldg(&fb1[c + 1]);
                    float g0 = gelu_fast(acc[mi][ni][0] + b0);
                    float g1 = gelu_fast(acc[mi][ni][1] + b1);
                    float g2 = gelu_fast(acc[mi][ni][2] + b0);
                    float g3 = gelu_fast(acc[mi][ni][3] + b1);
                    *(uint32_t*)&sA1[r * LDA1 + c]       = pack_h2(g0, g1);
                    *(uint32_t*)&sA1[(r + 8) * LDA1 + c] = pack_h2(g2, g3);
                }
        }

        // ---- GEMM2: Wf = gelu(A1 @ fw2 + fb2); fused register contraction ----
        for (int nc2 = 0; nc2 < 3; ++nc2) {
            float acc[2][4][4];
#pragma unroll
            for (int mi = 0; mi < 2; ++mi)
#pragma unroll
                for (int ni = 0; ni < 4; ++ni)
#pragma unroll
                    for (int r = 0; r < 4; ++r) acc[mi][ni][r] = 0.f;

            for (int kc = 0; kc < 3; ++kc)
                for (int kh = 0; kh < 2; ++kh) {
                    CP_WAIT0();
                    __syncthreads();   // also makes A1 visible at first iter
                    int nxt = hseq + 1; if (nxt == 24) nxt = 0;
                    cp_half(nxt, tid, sb);
                    CP_COMMIT();
                    do_ksteps4<LDA1>(aA1 + kc * 256 + kh * 128,
                                     bW0 + (uint32_t)(hseq & 1) * (SM_W1 - SM_W0), acc);
                    hseq = nxt;
                }

            // fused epilogue: fast gelu from acc, multiply hV, reduce
            {
                float colacc[8];
#pragma unroll
                for (int i = 0; i < 8; ++i) colacc[i] = 0.f;
                const float* hvb = hV + ((size_t)(b * L_) + mt * 64) * F_ + nc2 * 128;
#pragma unroll
                for (int mi = 0; mi < 2; ++mi)
#pragma unroll
                    for (int ni = 0; ni < 4; ++ni) {
                        int r  = m0w + mi * 16 + g;
                        int cc = n0w + ni * 8 + t * 2;
                        int c  = nc2 * 128 + cc;
                        float b0 = __ldg(&fb2[c]), b1 = __ldg(&fb2[c + 1]);
                        float2 hv0 = *(const float2*)(hvb + (size_t)r * F_ + cc);
                        float2 hv1 = *(const float2*)(hvb + (size_t)(r + 8) * F_ + cc);
                        colacc[ni * 2 + 0] += gelu_fast(acc[mi][ni][0] + b0) * hv0.x
                                            + gelu_fast(acc[mi][ni][2] + b0) * hv1.x;
                        colacc[ni * 2 + 1] += gelu_fast(acc[mi][ni][1] + b1) * hv0.y
                                            + gelu_fast(acc[mi][ni][3] + b1) * hv1.y;
                    }
#pragma unroll
                for (int i = 0; i < 8; ++i) {
                    colacc[i] += __shfl_down_sync(0xffffffffu, colacc[i], 16);
                    colacc[i] += __shfl_down_sync(0xffffffffu, colacc[i], 8);
                    colacc[i] += __shfl_down_sync(0xffffffffu, colacc[i], 4);
                }
                if (lane < 4) {
#pragma unroll
                    for (int ni = 0; ni < 4; ++ni) {
                        sPart[wid * 32 + ni * 8 + lane * 2 + 0] = colacc[ni * 2 + 0];
                        sPart[wid * 32 + ni * 8 + lane * 2 + 1] = colacc[ni * 2 + 1];
                    }
                }
            }
            __syncthreads();
            if (tid < 128) {
                int wq = tid >> 5, cc = tid & 31;
                float v = sPart[wq * 32 + cc] + sPart[(wq + 4) * 32 + cc];
                if (nc2 == 0)      xacc0 += v;
                else if (nc2 == 1) xacc1 += v;
                else               xacc2 += v;
            }
        }
    }

    CP_WAIT0();   // retire final wrapped prefetch

    // ---- head MLP (exact gelu) ----
    __syncthreads();
    if (tid < 128) {
        xcv[tid]       = xacc0;
        xcv[128 + tid] = xacc1;
        xcv[256 + tid] = xacc2;
    }
    __syncthreads();
    if (tid < 128) {
        float s = hb1[tid];
#pragma unroll 4
        for (int i = 0; i < F_; ++i) s += xcv[i] * hw1[i * H_ + tid];
        sH1[tid] = gelu_f(s);
    }
    __syncthreads();
    if (tid < 64) {
        float s = hb2[tid];
#pragma unroll 4
        for (int i = 0; i < H_; ++i) s += sH1[i] * hw2[i * 64 + tid];
        sH2[tid] = gelu_f(s);
    }
    __syncthreads();
    if (tid < 32) {
        float p = sH2[tid] * hw3[tid] + sH2[tid + 32] * hw3[tid + 32];
#pragma unroll
        for (int o = 16; o > 0; o >>= 1) p += __shfl_down_sync(0xffffffffu, p, o);
        if (tid == 0) {
            float pred = p + hb3[0];
            atomicAdd(&g_acc[b], pred * mask[b * L_ + l]);
        }
    }
}

__global__ void finalize_k(const float* __restrict__ mask, float* __restrict__ out) {
    int b = threadIdx.y, lane = threadIdx.x;
    float s = 0.f;
    for (int l = lane; l < L_; l += 32) s += mask[b * L_ + l];
#pragma unroll
    for (int o = 16; o > 0; o >>= 1) s += __shfl_down_sync(0xffffffffu, s, o);
    if (lane == 0) out[b] = g_acc[b] / sqrtf(fmaxf(s, 1.0f));
}

extern "C" void kernel_launch(void* const* d_in, const int* in_sizes, int n_in,
                              void* d_out, int out_size)
{
    const float* hV   = (const float*)d_in[0];
    const float* hE   = (const float*)d_in[1];
    const float* mask = (const float*)d_in[2];
    const float* fw1  = (const float*)d_in[3];
    const float* fb1  = (const float*)d_in[4];
    const float* fw2  = (const float*)d_in[5];
    const float* fb2  = (const float*)d_in[6];
    const float* hw1  = (const float*)d_in[7];
    const float* hb1  = (const float*)d_in[8];
    const float* hw2  = (const float*)d_in[9];
    const float* hb2  = (const float*)d_in[10];
    const float* hw3  = (const float*)d_in[11];
    const float* hb3  = (const float*)d_in[12];
    float* out = (float*)d_out;

    cudaFuncSetAttribute(fused_mma, cudaFuncAttributeMaxDynamicSharedMemorySize, SM_TOTAL);

    // 2 harness launches precede ours; with exactly 1 dummy, fused_mma is
    // launch index 5 -> ncu "-s 5 -c 1" profiles it.
    prep_weights<<<96, 256>>>(fw1, fw2);
    zero_acc_k<<<1, 32>>>();
    dummy_k<<<1, 32>>>();
    dim3 grid(L_, B_);
    fused_mma<<<grid, 256, SM_TOTAL>>>(hV, hE, mask, fb1, fb2,
                                       hw1, hb1, hw2, hb2, hw3, hb3);
    finalize_k<<<1, dim3(32, B_)>>>(mask, out);
}

// round 17
// speedup vs baseline: 1.3672x; 1.3430x over previous
#include <cuda_runtime.h>
#include <cuda_fp16.h>
#include <math.h>
#include <stdint.h>

#define B_ 4
#define L_ 384
#define H_ 128
#define F_ 384

typedef unsigned short ushort_t;

// ---------------- device scratch: fragment-ordered fp16 weight images --------
// frag[nt][kt][lane] = uint4 = the 4 B-regs lane needs for one n16 x k16 tile:
//   .x = W[n+(l>>2)][k+2(l&3)] pair,  .y = same n, k+8
//   .z = n+8 row,               .w = n+8, k+8
// fw1: nt 0..23 (N=384), kt 0..7  (K=128) -> 24*8*32 uint4
// fw2: nt 0..23 (N=384), kt 0..23 (K=384) -> 24*24*32 uint4
__device__ __align__(16) uint4 g_fw1F[24 * 8 * 32];
__device__ __align__(16) uint4 g_fw2F[24 * 24 * 32];
__device__ float g_acc[B_];

// ---------------- smem layout (bytes) ----------------------------------------
#define LDE   136   // halves per row (E tile: 64 x 128)
#define LDA1  392   // halves per row (A1: 64 x 384)

#define SM_E     0        // 17408
#define SM_A1    17408    // 50176
#define SM_XCV   67584    // 384 f = 1536
#define SM_PART  69120    // 512 f = 2048 (double-buffered 2x256)
#define SM_H1    71168    // 128 f
#define SM_H2    71680    // 64 f
#define SM_TOTAL 71936

// exact gelu (head MLP only)
__device__ __forceinline__ float gelu_f(float x) {
    return 0.5f * x * (1.0f + erff(x * 0.7071067811865475f));
}

// fast gelu: tanh formulation with HW MUFU.TANH
__device__ __forceinline__ float gelu_fast(float x) {
    float u = 0.7978845608028654f * x * (1.0f + 0.044715f * x * x);
    float t;
    asm("tanh.approx.f32 %0, %1;" : "=f"(t) : "f"(u));
    return 0.5f * x * (1.0f + t);
}

__device__ __forceinline__ uint32_t smem_u32(const void* p) {
    uint32_t a;
    asm("{ .reg .u64 t; cvta.to.shared.u64 t, %1; cvt.u32.u64 %0, t; }" : "=r"(a) : "l"(p));
    return a;
}

#define LDSM4(r, addr) \
    asm volatile("ldmatrix.sync.aligned.m8n8.x4.shared.b16 {%0,%1,%2,%3}, [%4];" \
        : "=r"((r)[0]), "=r"((r)[1]), "=r"((r)[2]), "=r"((r)[3]) : "r"(addr))

__device__ __forceinline__ void mma16816(float d[4], uint32_t a0, uint32_t a1,
                                         uint32_t a2, uint32_t a3,
                                         uint32_t b0, uint32_t b1) {
    asm volatile(
        "mma.sync.aligned.m16n8k16.row.col.f32.f16.f16.f32 "
        "{%0,%1,%2,%3}, {%4,%5,%6,%7}, {%8,%9}, {%0,%1,%2,%3};"
        : "+f"(d[0]), "+f"(d[1]), "+f"(d[2]), "+f"(d[3])
        : "r"(a0), "r"(a1), "r"(a2), "r"(a3), "r"(b0), "r"(b1));
}

__device__ __forceinline__ uint32_t pack_h2(float a, float b) {
    __half2 h = __floats2half2_rn(a, b);
    return *(uint32_t*)&h;
}

// NKS k-steps; A from SMEM (ldmatrix), B fragments via LDG.128 from frag image.
// fb0/fb1: frag pointers for p=0 / p=1 n-tiles, stride 32 uint4 per k-step.
template <int LDA, int NKS>
__device__ __forceinline__ void do_ksteps_ldg(
    uint32_t aA, const uint4* __restrict__ fb0, const uint4* __restrict__ fb1,
    float acc[2][4][4])
{
#pragma unroll
    for (int ks = 0; ks < NKS; ++ks) {
        uint32_t A[2][4];
        LDSM4(A[0], aA);
        LDSM4(A[1], aA + 16 * LDA * 2);
        aA += 32;
        uint4 f0 = __ldg(fb0 + ks * 32);
        uint4 f1 = __ldg(fb1 + ks * 32);
#pragma unroll
        for (int mi = 0; mi < 2; ++mi) {
            mma16816(acc[mi][0], A[mi][0], A[mi][1], A[mi][2], A[mi][3], f0.x, f0.y);
            mma16816(acc[mi][1], A[mi][0], A[mi][1], A[mi][2], A[mi][3], f0.z, f0.w);
            mma16816(acc[mi][2], A[mi][0], A[mi][1], A[mi][2], A[mi][3], f1.x, f1.y);
            mma16816(acc[mi][3], A[mi][0], A[mi][1], A[mi][2], A[mi][3], f1.z, f1.w);
        }
    }
}

// ---------------- weight prep: fragment-order fp16 images ---------------------
__global__ void prep_weights(const float* __restrict__ fw1,
                             const float* __restrict__ fw2) {
    int idx = blockIdx.x * blockDim.x + threadIdx.x;
    int stride = gridDim.x * blockDim.x;
    // fw1: [k(128)][n(384)] row-major source -> frag image (u32 granularity)
    for (int e = idx; e < 24 * 8 * 32 * 4; e += stride) {
        int j  = e & 3;
        int l  = (e >> 2) & 31;
        int kt = (e >> 7) & 7;
        int nt = e >> 10;
        int n = nt * 16 + ((j >> 1) & 1) * 8 + (l >> 2);
        int k = kt * 16 + (j & 1) * 8 + 2 * (l & 3);
        uint32_t v = pack_h2(fw1[(size_t)k * F_ + n], fw1[(size_t)(k + 1) * F_ + n]);
        ((uint32_t*)g_fw1F)[e] = v;
    }
    // fw2: [k(384)][n(384)]
    for (int e = idx; e < 24 * 24 * 32 * 4; e += stride) {
        int j  = e & 3;
        int l  = (e >> 2) & 31;
        int kt = (e >> 7) % 24;
        int nt = (e >> 7) / 24;
        int n = nt * 16 + ((j >> 1) & 1) * 8 + (l >> 2);
        int k = kt * 16 + (j & 1) * 8 + 2 * (l & 3);
        uint32_t v = pack_h2(fw2[(size_t)k * F_ + n], fw2[(size_t)(k + 1) * F_ + n]);
        ((uint32_t*)g_fw2F)[e] = v;
    }
}

__global__ void zero_acc_k() {
    if (threadIdx.x < B_) g_acc[threadIdx.x] = 0.f;
}

__global__ void dummy_k() {}

__global__ __launch_bounds__(256, 2) void fused_mma(
    const float* __restrict__ hV,  const float* __restrict__ hE,
    const float* __restrict__ mask,
    const float* __restrict__ fb1, const float* __restrict__ fb2,
    const float* __restrict__ hw1, const float* __restrict__ hb1,
    const float* __restrict__ hw2, const float* __restrict__ hb2,
    const float* __restrict__ hw3, const float* __restrict__ hb3)
{
    extern __shared__ char smem[];
    ushort_t* sE  = (ushort_t*)(smem + SM_E);
    ushort_t* sA1 = (ushort_t*)(smem + SM_A1);
    float* xcv   = (float*)(smem + SM_XCV);
    float* sPart = (float*)(smem + SM_PART);
    float* sH1   = (float*)(smem + SM_H1);
    float* sH2   = (float*)(smem + SM_H2);

    const uint32_t sb = smem_u32(smem);

    const int tid  = threadIdx.x;
    const int wid  = tid >> 5;
    const int lane = tid & 31;
    const int g    = lane >> 2;
    const int t    = lane & 3;
    const int m0w  = (wid >> 2) * 32;
    const int n0w  = (wid & 3) * 32;
    const int ntl  = n0w >> 4;          // local n-tile16 index (0,2,4,6)
    const int l = blockIdx.x, b = blockIdx.y;

    // ldmatrix per-lane addressing (A only)
    const int rA = lane & 15;
    const int kA = (lane >> 4) * 8;

    const uint32_t aE  = sb + SM_E  + ((m0w + rA) * LDE  + kA) * 2;
    const uint32_t aA1 = sb + SM_A1 + ((m0w + rA) * LDA1 + kA) * 2;

    float xacc0 = 0.f, xacc1 = 0.f, xacc2 = 0.f;
    const float* hE_base = hE + (size_t)(b * L_ + l) * L_ * H_;

    for (int mt = 0; mt < 6; ++mt) {
        // ---- stage E tile [64 x 128] fp32 -> fp16 ----
        {
            const float* src = hE_base + (size_t)(mt * 64) * H_;
#pragma unroll
            for (int it = 0; it < 8; ++it) {
                int gx = tid + it * 256;
                int m = gx >> 5, k4 = (gx & 31) * 4;
                float4 v = *(const float4*)(src + (size_t)m * H_ + k4);
                *(uint2*)&sE[m * LDE + k4] =
                    make_uint2(pack_h2(v.x, v.y), pack_h2(v.z, v.w));
            }
        }
        __syncthreads();   // E visible (and A1 from prev mt free: all k-loops done)

        // ---- GEMM1: A1 = gelu(E @ fw1 + fb1) -> sA1 fp16 (no barriers) ----
        for (int nc = 0; nc < 3; ++nc) {
            float acc[2][4][4];
#pragma unroll
            for (int mi = 0; mi < 2; ++mi)
#pragma unroll
                for (int ni = 0; ni < 4; ++ni)
#pragma unroll
                    for (int r = 0; r < 4; ++r) acc[mi][ni][r] = 0.f;

            const uint4* f0 = g_fw1F + ((size_t)(nc * 8 + ntl)     * 8) * 32 + lane;
            const uint4* f1 = g_fw1F + ((size_t)(nc * 8 + ntl + 1) * 8) * 32 + lane;
            do_ksteps_ldg<LDE, 8>(aE, f0, f1, acc);

            // epilogue: +bias, fast gelu, fp16 store
#pragma unroll
            for (int mi = 0; mi < 2; ++mi)
#pragma unroll
                for (int ni = 0; ni < 4; ++ni) {
                    int r = m0w + mi * 16 + g;
                    int c = nc * 128 + n0w + ni * 8 + t * 2;
                    float b0 = __ldg(&fb1[c]), b1 = __ldg(&fb1[c + 1]);
                    float g0 = gelu_fast(acc[mi][ni][0] + b0);
                    float g1 = gelu_fast(acc[mi][ni][1] + b1);
                    float g2 = gelu_fast(acc[mi][ni][2] + b0);
                    float g3 = gelu_fast(acc[mi][ni][3] + b1);
                    *(uint32_t*)&sA1[r * LDA1 + c]       = pack_h2(g0, g1);
                    *(uint32_t*)&sA1[(r + 8) * LDA1 + c] = pack_h2(g2, g3);
                }
        }
        __syncthreads();   // A1 visible to all warps

        // ---- GEMM2: Wf = gelu(A1 @ fw2 + fb2); fused register contraction ----
        for (int nc2 = 0; nc2 < 3; ++nc2) {
            float acc[2][4][4];
#pragma unroll
            for (int mi = 0; mi < 2; ++mi)
#pragma unroll
                for (int ni = 0; ni < 4; ++ni)
#pragma unroll
                    for (int r = 0; r < 4; ++r) acc[mi][ni][r] = 0.f;

            const uint4* f0 = g_fw2F + ((size_t)(nc2 * 8 + ntl)     * 24) * 32 + lane;
            const uint4* f1 = g_fw2F + ((size_t)(nc2 * 8 + ntl + 1) * 24) * 32 + lane;
            do_ksteps_ldg<LDA1, 24>(aA1, f0, f1, acc);

            // fused epilogue: fast gelu from acc, multiply hV, reduce
            float* sP = sPart + (nc2 & 1) * 256;
            {
                float colacc[8];
#pragma unroll
                for (int i = 0; i < 8; ++i) colacc[i] = 0.f;
                const float* hvb = hV + ((size_t)(b * L_) + mt * 64) * F_ + nc2 * 128;
#pragma unroll
                for (int mi = 0; mi < 2; ++mi)
#pragma unroll
                    for (int ni = 0; ni < 4; ++ni) {
                        int r  = m0w + mi * 16 + g;
                        int cc = n0w + ni * 8 + t * 2;
                        int c  = nc2 * 128 + cc;
                        float b0 = __ldg(&fb2[c]), b1 = __ldg(&fb2[c + 1]);
                        float2 hv0 = *(const float2*)(hvb + (size_t)r * F_ + cc);
                        float2 hv1 = *(const float2*)(hvb + (size_t)(r + 8) * F_ + cc);
                        colacc[ni * 2 + 0] += gelu_fast(acc[mi][ni][0] + b0) * hv0.x
                                            + gelu_fast(acc[mi][ni][2] + b0) * hv1.x;
                        colacc[ni * 2 + 1] += gelu_fast(acc[mi][ni][1] + b1) * hv0.y
                                            + gelu_fast(acc[mi][ni][3] + b1) * hv1.y;
                    }
#pragma unroll
                for (int i = 0; i < 8; ++i) {
                    colacc[i] += __shfl_down_sync(0xffffffffu, colacc[i], 16);
                    colacc[i] += __shfl_down_sync(0xffffffffu, colacc[i], 8);
                    colacc[i] += __shfl_down_sync(0xffffffffu, colacc[i], 4);
                }
                if (lane < 4) {
#pragma unroll
                    for (int ni = 0; ni < 4; ++ni) {
                        sP[wid * 32 + ni * 8 + lane * 2 + 0] = colacc[ni * 2 + 0];
                        sP[wid * 32 + ni * 8 + lane * 2 + 1] = colacc[ni * 2 + 1];
                    }
                }
            }
            __syncthreads();   // sP complete; also separates sP half reuse
            if (tid < 128) {
                int wq = tid >> 5, cc = tid & 31;
                float v = sP[wq * 32 + cc] + sP[(wq + 4) * 32 + cc];
                if (nc2 == 0)      xacc0 += v;
                else if (nc2 == 1) xacc1 += v;
                else               xacc2 += v;
            }
            // no trailing sync: next nc2 writes the other sPart half; the
            // half is re-written only after another full sync has passed.
        }
    }

    // ---- head MLP (exact gelu) ----
    __syncthreads();
    if (tid < 128) {
        xcv[tid]       = xacc0;
        xcv[128 + tid] = xacc1;
        xcv[256 + tid] = xacc2;
    }
    __syncthreads();
    if (tid < 128) {
        float s = hb1[tid];
#pragma unroll 4
        for (int i = 0; i < F_; ++i) s += xcv[i] * hw1[i * H_ + tid];
        sH1[tid] = gelu_f(s);
    }
    __syncthreads();
    if (tid < 64) {
        float s = hb2[tid];
#pragma unroll 4
        for (int i = 0; i < H_; ++i) s += sH1[i] * hw2[i * 64 + tid];
        sH2[tid] = gelu_f(s);
    }
    __syncthreads();
    if (tid < 32) {
        float p = sH2[tid] * hw3[tid] + sH2[tid + 32] * hw3[tid + 32];
#pragma unroll
        for (int o = 16; o > 0; o >>= 1) p += __shfl_down_sync(0xffffffffu, p, o);
        if (tid == 0) {
            float pred = p + hb3[0];
            atomicAdd(&g_acc[b], pred * mask[b * L_ + l]);
        }
    }
}

__global__ void finalize_k(const float* __restrict__ mask, float* __restrict__ out) {
    int b = threadIdx.y, lane = threadIdx.x;
    float s = 0.f;
    for (int l = lane; l < L_; l += 32) s += mask[b * L_ + l];
#pragma unroll
    for (int o = 16; o > 0; o >>= 1) s += __shfl_down_sync(0xffffffffu, s, o);
    if (lane == 0) out[b] = g_acc[b] / sqrtf(fmaxf(s, 1.0f));
}

extern "C" void kernel_launch(void* const* d_in, const int* in_sizes, int n_in,
                              void* d_out, int out_size)
{
    const float* hV   = (const float*)d_in[0];
    const float* hE   = (const float*)d_in[1];
    const float* mask = (const float*)d_in[2];
    const float* fw1  = (const float*)d_in[3];
    const float* fb1  = (const float*)d_in[4];
    const float* fw2  = (const float*)d_in[5];
    const float* fb2  = (const float*)d_in[6];
    const float* hw1  = (const float*)d_in[7];
    const float* hb1  = (const float*)d_in[8];
    const float* hw2  = (const float*)d_in[9];
    const float* hb2  = (const float*)d_in[10];
    const float* hw3  = (const float*)d_in[11];
    const float* hb3  = (const float*)d_in[12];
    float* out = (float*)d_out;

    cudaFuncSetAttribute(fused_mma, cudaFuncAttributeMaxDynamicSharedMemorySize, SM_TOTAL);

    // 2 harness launches precede ours; with exactly 1 dummy, fused_mma is
    // launch index 5 -> ncu "-s 5 -c 1" profiles it.
    prep_weights<<<96, 256>>>(fw1, fw2);
    zero_acc_k<<<1, 32>>>();
    dummy_k<<<1, 32>>>();
    dim3 grid(L_, B_);
    fused_mma<<<grid, 256, SM_TOTAL>>>(hV, hE, mask, fb1, fb2,
                                       hw1, hb1, hw2, hb2, hw3, hb3);
    finalize_k<<<1, dim3(32, B_)>>>(mask, out);
}